// round 16
// baseline (speedup 1.0000x reference)
#include <cuda_runtime.h>
#include <math.h>

#define BB   64
#define SIN  512
#define TOUT 64
#define HDIM 1024
#define VDIM 1024
#define GDIM 3072   // 3*HDIM
#define NBLK 128    // persistent-kernel grid size (co-resident, divides all phases)

// enc_scan smem: Wsh[24 rows][257 f4] + Ash[128][68] + Red[512][7 f4]
#define WSH_F (24*257*4)
#define ASH_F (128*68)
#define RED_F (512*7*4)
#define ENC_SMEM ((WSH_F + ASH_F + RED_F) * 4)

static const long OFF_HID = (long)BB*TOUT*VDIM;        // 4194304
static const long OFF_ATT = OFF_HID + 2L*BB*HDIM;      // 4325376

// ---------------- persistent scratch (device globals; no allocs) ----------------
__device__ float g_y0 [BB*SIN*HDIM];       // encoder layer-0 outputs   (134 MB)
__device__ float g_xp1[(long)BB*SIN*GDIM]; // precomputed y0 @ Wih1^T   (402 MB)
__device__ float g_enc[BB*SIN*HDIM];       // encoder layer-1 outputs   (134 MB)
__device__ float g_hb [2][2][BB*HDIM];     // h ping-pong per layer [layer][parity]
__device__ float g_part[8*BB*GDIM];        // decoder split-K partials
__device__ float g_q  [BB*HDIM];
__device__ float g_att[BB*HDIM];
__device__ float g_l1 [BB*HDIM];
__device__ float g_scores[BB*SIN];
__device__ float g_aw [BB*SIN];
__device__ int   g_tok[BB];

// ---------------- hierarchical grid barrier (16 leaf counters + root) -----------
__device__ unsigned g_cnt1[16*64];   // leaf counters, stride 64 uints = 256B
__device__ unsigned g_cnt2 = 0;      // root counter
__device__ unsigned g_gen  = 0;      // generation word

__device__ __forceinline__ void grid_sync() {
    __threadfence();
    __syncthreads();
    if (threadIdx.x == 0) {
        unsigned gen = *(volatile unsigned*)&g_gen;
        unsigned grp = blockIdx.x & 15u;
        bool release = false;
        if (atomicAdd(&g_cnt1[grp*64], 1u) == 7u) {        // last of 8-block group
            if (atomicAdd(&g_cnt2, 1u) == 15u) {           // last group overall
                #pragma unroll
                for (int i = 0; i < 16; i++) g_cnt1[i*64] = 0;
                g_cnt2 = 0;
                __threadfence();
                atomicAdd(&g_gen, 1u);
                release = true;
            }
        }
        if (!release)
            while (*(volatile unsigned*)&g_gen == gen) __nanosleep(20);
        __threadfence();
    }
    __syncthreads();
}

// ---------------- init (runs every launch) ----------------
__global__ void k_init() {
    int i = blockIdx.x*256 + threadIdx.x;      // 65536 threads
    g_hb[0][0][i] = 0.f; g_hb[0][1][i] = 0.f;
    g_hb[1][0][i] = 0.f; g_hb[1][1][i] = 0.f;
    if (i == 0) { g_cnt2 = 0; g_gen = 0; }
    if (i < 16*64) g_cnt1[i] = 0;
    if (i < BB) g_tok[i] = 0;
}

// ---------------- one 64x64xKlen tile (decoder path): split-K partial ------------
__device__ __forceinline__ void tile_mm(
    const float* __restrict__ A, long lda, const int* __restrict__ idx,
    const float* __restrict__ B, long ldb,
    int k0, int Klen, int n0, float* __restrict__ Cz, int N,
    float (&As)[16][68], float (&Bs)[16][68])
{
    const int tid = threadIdx.x;
    const int lr  = tid >> 2;
    const int lc  = (tid & 3) << 2;
    const int ty4 = (tid >> 4) << 2;
    const int tx4 = (tid & 15) << 2;

    long arow = idx ? (long)idx[lr]*lda : (long)lr*lda;
    const float* Ap = A + arow + k0 + lc;
    const float* Bp = B + (long)(n0 + lr)*ldb + k0 + lc;

    float acc[4][4] = {};
    float4 av = *(const float4*)Ap;
    float4 bv = *(const float4*)Bp;

    for (int kt = 0; kt < Klen; kt += 16) {
        As[lc+0][lr]=av.x; As[lc+1][lr]=av.y; As[lc+2][lr]=av.z; As[lc+3][lr]=av.w;
        Bs[lc+0][lr]=bv.x; Bs[lc+1][lr]=bv.y; Bs[lc+2][lr]=bv.z; Bs[lc+3][lr]=bv.w;
        __syncthreads();
        if (kt + 16 < Klen) {
            av = *(const float4*)(Ap + kt + 16);
            bv = *(const float4*)(Bp + kt + 16);
        }
        #pragma unroll
        for (int k = 0; k < 16; k++) {
            float4 a = *(const float4*)&As[k][ty4];
            float4 b = *(const float4*)&Bs[k][tx4];
            acc[0][0]+=a.x*b.x; acc[0][1]+=a.x*b.y; acc[0][2]+=a.x*b.z; acc[0][3]+=a.x*b.w;
            acc[1][0]+=a.y*b.x; acc[1][1]+=a.y*b.y; acc[1][2]+=a.y*b.z; acc[1][3]+=a.y*b.w;
            acc[2][0]+=a.z*b.x; acc[2][1]+=a.z*b.y; acc[2][2]+=a.z*b.z; acc[2][3]+=a.z*b.w;
            acc[3][0]+=a.w*b.x; acc[3][1]+=a.w*b.y; acc[3][2]+=a.w*b.z; acc[3][3]+=a.w*b.w;
        }
        __syncthreads();
    }
    float* Cp = Cz + (long)ty4*N + n0 + tx4;
    #pragma unroll
    for (int i = 0; i < 4; i++)
        *(float4*)(Cp + (long)i*N) = make_float4(acc[i][0],acc[i][1],acc[i][2],acc[i][3]);
}

// ---------------- persistent encoder GRU scan: fully fused, 1 barrier/step -------
// Block bid owns hh columns [bid*8, bid*8+8) and ALL THREE gate rows for them:
// 24 Whh rows resident in smem for the whole scan. Per step: chunked staging of
// full h (8 x 128k, [k][b] layout), 8-way k-split accumulation (thread kh owns
// granules g%8==kh), smem reduce, local GRU gate, write h ping-pong. No global
// partials, one grid barrier.
__global__ __launch_bounds__(512,1) void enc_scan(
    int layer, const float* __restrict__ x,
    const float* __restrict__ Wih,
    const float* __restrict__ Whh,
    const float* __restrict__ bih, const float* __restrict__ bhh)
{
    extern __shared__ float sm[];
    float* Wsh = sm;                  // [24 rows][257 float4]
    float* Ash = sm + WSH_F;          // [128 k][68]
    float* Red = sm + WSH_F + ASH_F;  // [512 thr][7 float4]

    const int tid = threadIdx.x;
    const int bid = blockIdx.x;
    const int hb  = bid * 8;          // owned hh base
    float* dst = (layer == 0) ? g_y0 : g_enc;

    // ---- load resident W slice: rows (e*8+hl) -> Whh[e*1024 + hb + hl] ----
    for (int idx = tid; idx < 24*256; idx += 512) {
        int row24 = idx >> 8;          // 0..23
        int gq    = idx & 255;         // k-granule
        int e = row24 >> 3, hl2 = row24 & 7;
        float4 v = *(const float4*)(Whh + (long)(e*1024 + hb + hl2)*1024 + gq*4);
        *(float4*)(Wsh + ((long)row24*257 + gq)*4) = v;
    }

    // thread roles
    const int kh  = tid >> 6;          // 0..7  k-split slice
    const int hp  = (tid >> 4) & 3;    // 0..3  hh-pair
    const int bq  = tid & 15;          // 0..15 batch-quad
    const int bq4 = bq * 4;
    const int am  = tid >> 3;          // staging row 0..63
    const int akq = tid & 7;           // staging k-phase
    // word offsets of this thread's 6 Wsh rows (r6 = e*2 + d)
    int rw[6];
    #pragma unroll
    for (int r6 = 0; r6 < 6; r6++) {
        int e = r6 >> 1, d = r6 & 1;
        rw[r6] = ((e*8 + hp*2 + d) * 257) * 4;
    }
    // gate-phase roles
    const int gb  = tid >> 3;          // batch 0..63
    const int hl  = tid & 7;           // local hh
    const int ghp = hl >> 1, gd = hl & 1;
    const int gbq = gb >> 2, gj = gb & 3;
    const int hh  = hb + hl;

    for (int t = 0; t < SIN; t++) {
        const float* hc = g_hb[layer][t & 1] + am*1024;
        float*       hw = g_hb[layer][(t + 1) & 1];

        float acc[6][4] = {};
        // prefetch chunk 0
        float4 v0 = *(const float4*)(hc + (akq+ 0)*4);
        float4 v1 = *(const float4*)(hc + (akq+ 8)*4);
        float4 v2 = *(const float4*)(hc + (akq+16)*4);
        float4 v3 = *(const float4*)(hc + (akq+24)*4);

        #pragma unroll
        for (int c = 0; c < 8; c++) {
            // scatter-store staged chunk: Ash[k][b]
            {
                int kq;
                kq = akq;      Ash[(kq*4+0)*68+am]=v0.x; Ash[(kq*4+1)*68+am]=v0.y; Ash[(kq*4+2)*68+am]=v0.z; Ash[(kq*4+3)*68+am]=v0.w;
                kq = akq + 8;  Ash[(kq*4+0)*68+am]=v1.x; Ash[(kq*4+1)*68+am]=v1.y; Ash[(kq*4+2)*68+am]=v1.z; Ash[(kq*4+3)*68+am]=v1.w;
                kq = akq + 16; Ash[(kq*4+0)*68+am]=v2.x; Ash[(kq*4+1)*68+am]=v2.y; Ash[(kq*4+2)*68+am]=v2.z; Ash[(kq*4+3)*68+am]=v2.w;
                kq = akq + 24; Ash[(kq*4+0)*68+am]=v3.x; Ash[(kq*4+1)*68+am]=v3.y; Ash[(kq*4+2)*68+am]=v3.z; Ash[(kq*4+3)*68+am]=v3.w;
            }
            __syncthreads();
            if (c < 7) {   // prefetch next chunk while computing this one
                const float* hn = hc + (c+1)*128;
                v0 = *(const float4*)(hn + (akq+ 0)*4);
                v1 = *(const float4*)(hn + (akq+ 8)*4);
                v2 = *(const float4*)(hn + (akq+16)*4);
                v3 = *(const float4*)(hn + (akq+24)*4);
            }
            // compute: this thread's 4 granules in the chunk (g%8 == kh)
            #pragma unroll
            for (int jj = 0; jj < 4; jj++) {
                int gg = jj*8 + kh;          // granule in chunk
                int kb = gg*4;               // k base in chunk
                float4 A0 = *(const float4*)&Ash[(kb+0)*68 + bq4];
                float4 A1 = *(const float4*)&Ash[(kb+1)*68 + bq4];
                float4 A2 = *(const float4*)&Ash[(kb+2)*68 + bq4];
                float4 A3 = *(const float4*)&Ash[(kb+3)*68 + bq4];
                const float* wg = Wsh + (long)(c*32 + gg)*4;
                float a[4][4] = {{A0.x,A0.y,A0.z,A0.w},{A1.x,A1.y,A1.z,A1.w},
                                 {A2.x,A2.y,A2.z,A2.w},{A3.x,A3.y,A3.z,A3.w}};
                #pragma unroll
                for (int r = 0; r < 6; r++) {
                    float4 W = *(const float4*)(wg + rw[r]);
                    float w[4] = {W.x, W.y, W.z, W.w};
                    #pragma unroll
                    for (int i = 0; i < 4; i++)
                        #pragma unroll
                        for (int j = 0; j < 4; j++)
                            acc[r][j] += a[i][j] * w[i];
                }
            }
            __syncthreads();
        }

        // ---- intra-block k-split reduction through shared ----
        #pragma unroll
        for (int r6 = 0; r6 < 6; r6++)
            *(float4*)(Red + ((long)tid*7 + r6)*4) =
                make_float4(acc[r6][0], acc[r6][1], acc[r6][2], acc[r6][3]);
        __syncthreads();

        // ---- gate: one (b, hh) per thread ----
        {
            float s0 = 0.f, s1 = 0.f, s2 = 0.f;
            #pragma unroll
            for (int k2 = 0; k2 < 8; k2++) {
                int base = (k2*64 + ghp*16 + gbq) * 7;
                s0 += Red[(base + 0 + gd)*4 + gj];
                s1 += Red[(base + 2 + gd)*4 + gj];
                s2 += Red[(base + 4 + gd)*4 + gj];
            }
            float xr, xz, xn;
            if (layer == 0) {
                float x0 = x[(gb*2  )*SIN + t];
                float x1 = x[(gb*2+1)*SIN + t];
                xr = x0*Wih[2*hh]          + x1*Wih[2*hh+1]          + bih[hh];
                xz = x0*Wih[2*(HDIM+hh)]   + x1*Wih[2*(HDIM+hh)+1]   + bih[HDIM+hh];
                xn = x0*Wih[2*(2*HDIM+hh)] + x1*Wih[2*(2*HDIM+hh)+1] + bih[2*HDIM+hh];
            } else {
                const float* xp = g_xp1 + (long)(gb*SIN + t)*GDIM;
                xr = xp[hh]        + bih[hh];
                xz = xp[HDIM+hh]   + bih[HDIM+hh];
                xn = xp[2*HDIM+hh] + bih[2*HDIM+hh];
            }
            float hrv = s0 + bhh[hh];
            float hzv = s1 + bhh[HDIM+hh];
            float hnv = s2 + bhh[2*HDIM+hh];
            float r  = 1.f/(1.f + expf(-(xr+hrv)));
            float zg = 1.f/(1.f + expf(-(xz+hzv)));
            float n  = tanhf(xn + r*hnv);
            float hold = g_hb[layer][t & 1][gb*HDIM + hh];
            float hnew = (1.f - zg)*n + zg*hold;
            hw[gb*HDIM + hh] = hnew;
            dst[(long)(gb*SIN + t)*HDIM + hh] = hnew;
        }
        grid_sync();
    }
}

// ---------------- big GEMM: xp1 = y0 @ Wih1^T; 128x128 tile, 8x8 microtile ------
__global__ __launch_bounds__(256) void gemm_big(
    const float* __restrict__ A, const float* __restrict__ B,
    float* __restrict__ C, int N, int K)
{
    __shared__ float As[16*132];   // [k][m], m=128
    __shared__ float Bs[16*132];   // [k][n], n=128
    const int m0 = blockIdx.y * 128, n0 = blockIdx.x * 128;
    const int tid = threadIdx.x;
    const int lr  = tid >> 1, lc = (tid & 1) * 8;     // 2 float4 per thread per mat
    const int ty4 = ((tid >> 4) & 15) * 4;
    const int tx4 = (tid & 15) * 4;

    const float* Ap = A + (long)(m0 + lr)*K + lc;
    const float* Bp = B + (long)(n0 + lr)*K + lc;

    float acc[8][8] = {};
    float4 av0 = *(const float4*)Ap;
    float4 av1 = *(const float4*)(Ap + 4);
    float4 bv0 = *(const float4*)Bp;
    float4 bv1 = *(const float4*)(Bp + 4);

    for (int kt = 0; kt < K; kt += 16) {
        As[(lc+0)*132+lr]=av0.x; As[(lc+1)*132+lr]=av0.y;
        As[(lc+2)*132+lr]=av0.z; As[(lc+3)*132+lr]=av0.w;
        As[(lc+4)*132+lr]=av1.x; As[(lc+5)*132+lr]=av1.y;
        As[(lc+6)*132+lr]=av1.z; As[(lc+7)*132+lr]=av1.w;
        Bs[(lc+0)*132+lr]=bv0.x; Bs[(lc+1)*132+lr]=bv0.y;
        Bs[(lc+2)*132+lr]=bv0.z; Bs[(lc+3)*132+lr]=bv0.w;
        Bs[(lc+4)*132+lr]=bv1.x; Bs[(lc+5)*132+lr]=bv1.y;
        Bs[(lc+6)*132+lr]=bv1.z; Bs[(lc+7)*132+lr]=bv1.w;
        __syncthreads();
        if (kt + 16 < K) {
            av0 = *(const float4*)(Ap + kt + 16);
            av1 = *(const float4*)(Ap + kt + 20);
            bv0 = *(const float4*)(Bp + kt + 16);
            bv1 = *(const float4*)(Bp + kt + 20);
        }
        #pragma unroll
        for (int k = 0; k < 16; k++) {
            float4 a0 = *(const float4*)&As[k*132 + ty4];
            float4 a1 = *(const float4*)&As[k*132 + ty4 + 64];
            float4 b0 = *(const float4*)&Bs[k*132 + tx4];
            float4 b1 = *(const float4*)&Bs[k*132 + tx4 + 64];
            float am[8] = {a0.x,a0.y,a0.z,a0.w, a1.x,a1.y,a1.z,a1.w};
            float bn[8] = {b0.x,b0.y,b0.z,b0.w, b1.x,b1.y,b1.z,b1.w};
            #pragma unroll
            for (int i = 0; i < 8; i++)
                #pragma unroll
                for (int j = 0; j < 8; j++)
                    acc[i][j] += am[i]*bn[j];
        }
        __syncthreads();
    }
    #pragma unroll
    for (int ib = 0; ib < 2; ib++)
        #pragma unroll
        for (int i = 0; i < 4; i++) {
            float* row = C + (long)(m0 + ty4 + ib*64 + i)*N + n0;
            *(float4*)(row + tx4)      = make_float4(acc[ib*4+i][0],acc[ib*4+i][1],
                                                     acc[ib*4+i][2],acc[ib*4+i][3]);
            *(float4*)(row + tx4 + 64) = make_float4(acc[ib*4+i][4],acc[ib*4+i][5],
                                                     acc[ib*4+i][6],acc[ib*4+i][7]);
        }
}

// ---------------- persistent decoder: all 64 greedy autoregressive steps --------
__global__ __launch_bounds__(256,2) void dec_scan(
    const float* __restrict__ emb,
    const float* __restrict__ dWih0, const float* __restrict__ dWhh0,
    const float* __restrict__ dbih0, const float* __restrict__ dbhh0,
    const float* __restrict__ dWih1, const float* __restrict__ dWhh1,
    const float* __restrict__ dbih1, const float* __restrict__ dbhh1,
    const float* __restrict__ hqW,  const float* __restrict__ hqb,
    const float* __restrict__ combW,const float* __restrict__ combb,
    const float* __restrict__ fcW,  const float* __restrict__ fcb,
    float* __restrict__ out, float* __restrict__ outAtt)
{
    __shared__ float As[16][68], Bs[16][68];
    const int tid  = threadIdx.x;
    const int nthr = gridDim.x * blockDim.x;
    const int gtid = blockIdx.x * blockDim.x + tid;
    float* h0 = g_hb[0][0];
    float* h1 = g_hb[1][0];

    for (int t = 0; t < TOUT; t++) {
        // ---- layer 0 GEMM: emb[tok]@Wih0^T (z 0..3) + h0@Whh0^T (z 4..7) ----
        for (int tile = blockIdx.x; tile < 128; tile += gridDim.x) {
            int z = tile >> 4, nt = tile & 15;
            if (z < 4)
                tile_mm(emb, 1024, g_tok, dWih0, 1024, z*256, 256, nt*64,
                        g_part + (long)z*64*1024, 1024, As, Bs);
            else
                tile_mm(h0, 1024, (const int*)0, dWhh0, 1024, (z-4)*256, 256, nt*64,
                        g_part + (long)z*64*1024, 1024, As, Bs);
        }
        grid_sync();
        for (int i = gtid; i < BB*HDIM; i += nthr) {
            int b = i >> 10, n = i & 1023;
            float s = dbih0[n] + dbhh0[n];
            #pragma unroll
            for (int z = 0; z < 8; z++) s += g_part[(long)(z*64 + b)*1024 + n];
            h0[i] = tanhf(s);
        }
        grid_sync();
        // ---- layer 1 GEMM ----
        for (int tile = blockIdx.x; tile < 128; tile += gridDim.x) {
            int z = tile >> 4, nt = tile & 15;
            if (z < 4)
                tile_mm(h0, 1024, (const int*)0, dWih1, 1024, z*256, 256, nt*64,
                        g_part + (long)z*64*1024, 1024, As, Bs);
            else
                tile_mm(h1, 1024, (const int*)0, dWhh1, 1024, (z-4)*256, 256, nt*64,
                        g_part + (long)z*64*1024, 1024, As, Bs);
        }
        grid_sync();
        for (int i = gtid; i < BB*HDIM; i += nthr) {
            int b = i >> 10, n = i & 1023;
            float s = dbih1[n] + dbhh1[n];
            #pragma unroll
            for (int z = 0; z < 8; z++) s += g_part[(long)(z*64 + b)*1024 + n];
            h1[i] = tanhf(s);
        }
        grid_sync();
        // ---- q = h1 @ hqW^T + hqb ----
        for (int tile = blockIdx.x; tile < 128; tile += gridDim.x) {
            int z = tile >> 4, nt = tile & 15;
            tile_mm(h1, 1024, (const int*)0, hqW, 1024, z*128, 128, nt*64,
                    g_part + (long)z*64*1024, 1024, As, Bs);
        }
        grid_sync();
        for (int i = gtid; i < BB*HDIM; i += nthr) {
            int b = i >> 10, n = i & 1023;
            float s = hqb[n];
            #pragma unroll
            for (int z = 0; z < 8; z++) s += g_part[(long)(z*64 + b)*1024 + n];
            g_q[i] = s;
        }
        grid_sync();
        // ---- scores[b,s] = enc[b,s,:] . q[b] ----
        for (int u = blockIdx.x; u < 1024; u += gridDim.x) {
            int b = u >> 4, sc = u & 15;
            float* qs = &As[0][0];
            __syncthreads();
            for (int j = tid; j < HDIM; j += 256) qs[j] = g_q[b*HDIM + j];
            __syncthreads();
            int sl = tid >> 3, kp = tid & 7;
            int s  = sc*32 + sl;
            const float* e = g_enc + (long)(b*SIN + s)*HDIM;
            float acc = 0.f;
            #pragma unroll 4
            for (int i2 = 0; i2 < 32; i2++) {
                int k = i2*32 + kp*4;
                float4 ev = *(const float4*)(e + k);
                acc += ev.x*qs[k] + ev.y*qs[k+1] + ev.z*qs[k+2] + ev.w*qs[k+3];
            }
            acc += __shfl_xor_sync(0xffffffffu, acc, 4);
            acc += __shfl_xor_sync(0xffffffffu, acc, 2);
            acc += __shfl_xor_sync(0xffffffffu, acc, 1);
            if (kp == 0) g_scores[b*SIN + s] = acc;
            __syncthreads();
        }
        grid_sync();
        // ---- softmax over s (blocks 0..63) ----
        if (blockIdx.x < 64) {
            int b = blockIdx.x;
            float* red = &As[0][0];
            float v0 = g_scores[b*SIN + tid], v1 = g_scores[b*SIN + 256 + tid];
            red[tid] = fmaxf(v0, v1); __syncthreads();
            for (int w = 128; w > 0; w >>= 1) {
                if (tid < w) red[tid] = fmaxf(red[tid], red[tid+w]);
                __syncthreads();
            }
            float mx = red[0]; __syncthreads();
            float e0 = expf(v0 - mx), e1 = expf(v1 - mx);
            red[tid] = e0 + e1; __syncthreads();
            for (int w = 128; w > 0; w >>= 1) {
                if (tid < w) red[tid] += red[tid+w];
                __syncthreads();
            }
            float inv = 1.f/red[0];
            float a0 = e0*inv, a1 = e1*inv;
            g_aw[b*SIN + tid] = a0; g_aw[b*SIN + 256 + tid] = a1;
            if (t == TOUT-1) { outAtt[b*SIN + tid] = a0; outAtt[b*SIN + 256 + tid] = a1; }
        }
        grid_sync();
        // ---- att[b,h] = sum_s aw[s]*enc[b,s,h] ----
        for (int u = blockIdx.x; u < 256; u += gridDim.x) {
            int hc = u & 3, b = u >> 2;
            float* aw = &As[0][0];
            __syncthreads();
            for (int j = tid; j < SIN; j += 256) aw[j] = g_aw[b*SIN + j];
            __syncthreads();
            int hh = hc*256 + tid;
            const float* e = g_enc + (long)b*SIN*HDIM + hh;
            float acc = 0.f;
            #pragma unroll 8
            for (int s = 0; s < SIN; s++) acc += aw[s]*e[(long)s*HDIM];
            g_att[b*HDIM + hh] = acc;
            __syncthreads();
        }
        grid_sync();
        // ---- l1 = [h1|att] @ combW^T + combb ----
        for (int tile = blockIdx.x; tile < 128; tile += gridDim.x) {
            int z = tile >> 4, nt = tile & 15;
            if (z < 4)
                tile_mm(h1, 1024, (const int*)0, combW, 2048, z*256, 256, nt*64,
                        g_part + (long)z*64*1024, 1024, As, Bs);
            else
                tile_mm(g_att, 1024, (const int*)0, combW + 1024, 2048, (z-4)*256, 256, nt*64,
                        g_part + (long)z*64*1024, 1024, As, Bs);
        }
        grid_sync();
        for (int i = gtid; i < BB*HDIM; i += nthr) {
            int b = i >> 10, n = i & 1023;
            float s = combb[n];
            #pragma unroll
            for (int z = 0; z < 8; z++) s += g_part[(long)(z*64 + b)*1024 + n];
            g_l1[i] = s;
        }
        grid_sync();
        // ---- logits = l1 @ fcW^T + fcb -> out[:, t, :] ----
        for (int tile = blockIdx.x; tile < 128; tile += gridDim.x) {
            int z = tile >> 4, nt = tile & 15;
            tile_mm(g_l1, 1024, (const int*)0, fcW, 1024, z*128, 128, nt*64,
                    g_part + (long)z*64*1024, 1024, As, Bs);
        }
        grid_sync();
        for (int i = gtid; i < BB*VDIM; i += nthr) {
            int b = i >> 10, v = i & 1023;
            float s = fcb[v];
            #pragma unroll
            for (int z = 0; z < 8; z++) s += g_part[(long)(z*64 + b)*1024 + v];
            out[(long)(b*TOUT + t)*VDIM + v] = s;
        }
        grid_sync();
        // ---- argmax (first-max ties) -> g_tok; skip on last step ----
        if (t < TOUT-1) {
            if (blockIdx.x < 64) {
                int b = blockIdx.x;
                float* sv = &As[0][0];
                int*   si = (int*)&Bs[0][0];
                const float* l = out + (long)(b*TOUT + t)*VDIM;
                float best = -3.4e38f; int bi = 0;
                #pragma unroll
                for (int j = 0; j < 4; j++) {
                    int idx = tid*4 + j;
                    float v = l[idx];
                    if (v > best) { best = v; bi = idx; }
                }
                sv[tid] = best; si[tid] = bi; __syncthreads();
                for (int w = 128; w > 0; w >>= 1) {
                    if (tid < w) {
                        float v2 = sv[tid+w]; int i2 = si[tid+w];
                        if (v2 > sv[tid] || (v2 == sv[tid] && i2 < si[tid])) {
                            sv[tid] = v2; si[tid] = i2;
                        }
                    }
                    __syncthreads();
                }
                if (tid == 0) g_tok[b] = si[0];
            }
            grid_sync();
        }
    }
}

__global__ void k_copy_hidden(float* __restrict__ out) {   // 512 x 256
    int i = blockIdx.x*256 + threadIdx.x;                  // 131072
    int l = i >> 16;
    out[i] = g_hb[l][0][i & 65535];
}

// ---------------- host ----------------
extern "C" void kernel_launch(void* const* d_in, const int* in_sizes, int n_in,
                              void* d_out, int out_size)
{
    (void)n_in; (void)out_size;
    // in_sizes[6]: signature order -> enc_Wih1 (3145728); dict order -> dec_Wih0 (1048576)
    bool sig = (in_sizes[6] == 3145728);
    const float* x   = (const float*)d_in[0];
    const float* emb = (const float*)d_in[1];
    const float *eWih0,*eWhh0,*ebih0,*ebhh0,*eWih1,*eWhh1,*ebih1,*ebhh1;
    const float *dWih0,*dWhh0,*dbih0,*dbhh0,*dWih1,*dWhh1,*dbih1,*dbhh1;
    if (sig) {
        eWih0=(const float*)d_in[2];  eWhh0=(const float*)d_in[3];
        ebih0=(const float*)d_in[4];  ebhh0=(const float*)d_in[5];
        eWih1=(const float*)d_in[6];  eWhh1=(const float*)d_in[7];
        ebih1=(const float*)d_in[8];  ebhh1=(const float*)d_in[9];
        dWih0=(const float*)d_in[10]; dWhh0=(const float*)d_in[11];
        dbih0=(const float*)d_in[12]; dbhh0=(const float*)d_in[13];
        dWih1=(const float*)d_in[14]; dWhh1=(const float*)d_in[15];
        dbih1=(const float*)d_in[16]; dbhh1=(const float*)d_in[17];
    } else {
        eWih0=(const float*)d_in[2];  eWhh0=(const float*)d_in[3];
        ebih0=(const float*)d_in[4];  ebhh0=(const float*)d_in[5];
        dWih0=(const float*)d_in[6];  dWhh0=(const float*)d_in[7];
        dbih0=(const float*)d_in[8];  dbhh0=(const float*)d_in[9];
        eWih1=(const float*)d_in[10]; eWhh1=(const float*)d_in[11];
        ebih1=(const float*)d_in[12]; ebhh1=(const float*)d_in[13];
        dWih1=(const float*)d_in[14]; dWhh1=(const float*)d_in[15];
        dbih1=(const float*)d_in[16]; dbhh1=(const float*)d_in[17];
    }
    const float* hq_W   = (const float*)d_in[18];
    const float* hq_b   = (const float*)d_in[19];
    const float* comb_W = (const float*)d_in[20];
    const float* comb_b = (const float*)d_in[21];
    const float* fc_W   = (const float*)d_in[22];
    const float* fc_b   = (const float*)d_in[23];
    float* out = (float*)d_out;

    float *p_y0, *p_xp1;
    cudaGetSymbolAddress((void**)&p_y0,  g_y0);
    cudaGetSymbolAddress((void**)&p_xp1, g_xp1);
    cudaFuncSetAttribute(enc_scan, cudaFuncAttributeMaxDynamicSharedMemorySize, ENC_SMEM);

    k_init<<<256,256>>>();

    // encoder layer 0 (512-step scan, fused GEMM+gate, 1 barrier/step)
    enc_scan<<<NBLK,512,ENC_SMEM>>>(0, x, eWih0, eWhh0, ebih0, ebhh0);
    // xp1 = y0 @ Wih1^T (one big parallel GEMM, 128x128 tile)
    gemm_big<<<dim3(24,256),256>>>(p_y0, eWih1, p_xp1, GDIM, 1024);
    // encoder layer 1
    enc_scan<<<NBLK,512,ENC_SMEM>>>(1, x, eWih1, eWhh1, ebih1, ebhh1);
    // decoder (64 greedy steps, one node)
    dec_scan<<<NBLK,256>>>(emb,
                           dWih0, dWhh0, dbih0, dbhh0,
                           dWih1, dWhh1, dbih1, dbhh1,
                           hq_W, hq_b, comb_W, comb_b, fc_W, fc_b,
                           out, out + OFF_ATT);
    // hidden [2, B, H]
    k_copy_hidden<<<512,256>>>(out + OFF_HID);
}